// round 3
// baseline (speedup 1.0000x reference)
#include <cuda_runtime.h>
#include <cuda_fp16.h>
#include <cstdint>
#include <cstddef>

#define NB 4
#define NN 4096
#define ND 256
#define NOUT 64
#define NROWS (NB*NN)

// ---------------- device scratch ----------------
__device__ __align__(16) float g_avec[256];
__device__ __align__(16) float g_beff[64];
__device__ float g_csrc;
__device__ __align__(16) float g_Wc[256*66];          // [d][l]: l<64 Weff, l=64 a_vec, l=65 zero
__device__ __align__(16) float g_hs[(size_t)NROWS*64];
__device__ __align__(16) float g_src[NROWS];
__device__ float g_max[NB];
__device__ __align__(16) __half g_whT[(size_t)NB*72*4096]; // [b][l(72)][j]; l=64 is w, 65..71 zero

// ---------------- helpers ----------------
static __device__ __forceinline__ void cp16(void* s, const void* g) {
  uint32_t sa = (uint32_t)__cvta_generic_to_shared(s);
  asm volatile("cp.async.cg.shared.global [%0], [%1], 16;\n" :: "r"(sa), "l"(g));
}
#define CP_COMMIT() asm volatile("cp.async.commit_group;\n" ::)
#define CP_WAIT2()  asm volatile("cp.async.wait_group 2;\n" ::)

static __device__ __forceinline__ uint32_t f2h2(float x, float y) {
  __half2 h = __floats2half2_rn(x, y);
  return *reinterpret_cast<uint32_t*>(&h);
}
static __device__ __forceinline__ void mma16816(float c[4],
    uint32_t a0, uint32_t a1, uint32_t a2, uint32_t a3, uint32_t b0, uint32_t b1) {
  asm volatile("mma.sync.aligned.m16n8k16.row.col.f32.f16.f16.f32 "
    "{%0,%1,%2,%3}, {%4,%5,%6,%7}, {%8,%9}, {%0,%1,%2,%3};\n"
    : "+f"(c[0]), "+f"(c[1]), "+f"(c[2]), "+f"(c[3])
    : "r"(a0), "r"(a1), "r"(a2), "r"(a3), "r"(b0), "r"(b1));
}

// ---------------- K0a: fold attention weights ----------------
__global__ void k0a(const float* __restrict__ W_fc, const float* __restrict__ b_fc,
                    const float* __restrict__ W_attn) {
  __shared__ float ws[256];
  const int t = threadIdx.x;
  {
    int h = t >> 6, o = t & 63;
    float s = 0.f;
    #pragma unroll
    for (int k = 0; k < 4; k++) s += W_attn[k*512 + h*128 + o];
    ws[t] = 0.25f * s;
  }
  __syncthreads();
  {
    float a0 = 0.f, a1 = 0.f;
    for (int c = 0; c < 256; c += 2) {
      a0 += ws[c]   * W_fc[(size_t)c*256 + t];
      a1 += ws[c+1] * W_fc[(size_t)(c+1)*256 + t];
    }
    g_avec[t] = a0 + a1;
  }
  if (t < 64) {
    float bb = 0.f;
    #pragma unroll
    for (int h = 0; h < 4; h++) bb += b_fc[h*64 + t];
    g_beff[t] = bb;
  }
  if (t == 0) {
    float cs = 0.f;
    for (int c = 0; c < 256; c++) cs += b_fc[c] * ws[c];
    g_csrc = cs;
  }
}

// ---------------- K0b: combined weight matrix [256][66] ----------------
__global__ void k0b(const float* __restrict__ W_fc) {
  int d = blockIdx.x;
  int l = threadIdx.x;
  if (l >= 66) return;
  float v = 0.f;
  if (l < 64) {
    #pragma unroll
    for (int h = 0; h < 4; h++) v += W_fc[(size_t)(h*64 + l)*256 + d];
  } else if (l == 64) {
    v = g_avec[d];
  }
  g_Wc[d*66 + l] = v;
}

// ---------------- K1: hs = F@Weff + beff ; src = F@a_vec + csrc ----------------
__global__ void __launch_bounds__(128) k1(const float* __restrict__ F) {
  __shared__ float Fs[128][33];
  __shared__ float Ws[32][66];
  const int t = threadIdx.x;
  const int rowbase = blockIdx.x * 128;
  const int l0 = blockIdx.y * 33;   // 0 or 33
  float acc[33];
  #pragma unroll
  for (int i = 0; i < 33; i++) acc[i] = 0.f;

  for (int c = 0; c < 8; ++c) {
    const int d0 = c * 32;
    __syncthreads();
    #pragma unroll
    for (int i = 0; i < 32; ++i) {
      int idx = i*128 + t;
      int rr = idx >> 5, dd = idx & 31;
      Fs[rr][dd] = F[(size_t)(rowbase + rr)*256 + d0 + dd];
    }
    for (int i = t; i < 32*66; i += 128) {
      int dd = i / 66, l = i - dd*66;
      Ws[dd][l] = g_Wc[(d0 + dd)*66 + l];
    }
    __syncthreads();
    #pragma unroll 4
    for (int dd = 0; dd < 32; ++dd) {
      float f = Fs[t][dd];
      #pragma unroll
      for (int i = 0; i < 33; ++i) acc[i] = fmaf(f, Ws[dd][l0 + i], acc[i]);
    }
  }
  const int row = rowbase + t;
  #pragma unroll
  for (int i = 0; i < 33; ++i) {
    int l = l0 + i;
    if (l < 64)       g_hs[(size_t)row*64 + l] = acc[i] + g_beff[l];
    else if (l == 64) g_src[row] = acc[i] + g_csrc;
  }
}

// ---------------- K2: per-batch max of src ----------------
__global__ void k2() {
  __shared__ float red[256];
  const int b = blockIdx.x, t = threadIdx.x;
  float m = -1e30f;
  for (int j = t; j < NN; j += 256) m = fmaxf(m, g_src[b*NN + j]);
  red[t] = m;
  __syncthreads();
  for (int s = 128; s > 0; s >>= 1) {
    if (t < s) red[t] = fmaxf(red[t], red[t + s]);
    __syncthreads();
  }
  if (t == 0) g_max[b] = red[0];
}

// ---------------- K3: build transposed fp16 [w*hs | w | 0] ----------------
__global__ void __launch_bounds__(256) k3() {
  __shared__ float sh[64][65];
  __shared__ float wsm[64];
  const int t = threadIdx.x;
  const int jbase = blockIdx.x * 64;
  const int b = blockIdx.y;
  // stage hs tile [64 j][64 l]
  for (int idx = t; idx < 64*64; idx += 256) {
    int jl = idx >> 6, l = idx & 63;
    sh[jl][l] = g_hs[(size_t)(b*NN + jbase + jl)*64 + l];
  }
  if (t < 64) {
    wsm[t] = expf(g_src[b*NN + jbase + t] - g_max[b]);
  }
  __syncthreads();
  for (int idx = t; idx < 72*64; idx += 256) {
    int l = idx >> 6, jl = idx & 63;
    float v;
    if (l < 64)       v = wsm[jl] * sh[jl][l];
    else if (l == 64) v = wsm[jl];
    else              v = 0.f;
    g_whT[((size_t)b*72 + l)*4096 + jbase + jl] = __float2half(v);
  }
}

// ---------------- K4: per-batch C[4096,72] = adj @ [wh|w], fused normalize ----------------
__global__ void __launch_bounds__(256) k4(const float* __restrict__ adj,
                                          float* __restrict__ out) {
  __shared__ __half sb[4][72][40];   // 80B-padded rows: conflict-free fragment loads
  const int t = threadIdx.x;
  const int warp = t >> 5, lane = t & 31;
  const int g = lane >> 2, tig = lane & 3;
  const int b = blockIdx.y;
  const int rowbase = blockIdx.x * 128 + warp * 16;
  const float* adjb = adj + ((size_t)b << 24);
  const __half* wht = g_whT + (size_t)b * 72 * 4096;

  float c[9][4];
  #pragma unroll
  for (int nt = 0; nt < 9; nt++) {
    #pragma unroll
    for (int i = 0; i < 4; i++) c[nt][i] = 0.f;
  }

  const float* arow0 = adjb + (size_t)(rowbase + g) * 4096;
  const float* arow1 = adjb + (size_t)(rowbase + g + 8) * 4096;

  // producer: stage sk covers k [sk*32, sk*32+32)
  auto issue = [&](int sk) {
    const int slot = sk & 3;
    const int kbase = sk * 32;
    for (int i = t; i < 288; i += 256) {
      int n = i >> 2, cc = i & 3;
      cp16(&sb[slot][n][cc*8], wht + (size_t)n*4096 + kbase + cc*8);
    }
  };

  issue(0); CP_COMMIT();
  issue(1); CP_COMMIT();
  issue(2); CP_COMMIT();

  for (int sk = 0; sk < 128; ++sk) {
    CP_WAIT2();
    __syncthreads();
    if (sk + 3 < 128) issue(sk + 3);
    CP_COMMIT();                       // empty commits in tail keep group count uniform
    const int slot = sk & 3;
    #pragma unroll
    for (int ks = 0; ks < 2; ++ks) {
      const int k0 = sk*32 + ks*16 + tig*2;
      float2 f0 = __ldcs(reinterpret_cast<const float2*>(arow0 + k0));
      float2 f1 = __ldcs(reinterpret_cast<const float2*>(arow1 + k0));
      float2 f2 = __ldcs(reinterpret_cast<const float2*>(arow0 + k0 + 8));
      float2 f3 = __ldcs(reinterpret_cast<const float2*>(arow1 + k0 + 8));
      uint32_t a0 = f2h2(f0.x, f0.y);
      uint32_t a1 = f2h2(f1.x, f1.y);
      uint32_t a2 = f2h2(f2.x, f2.y);
      uint32_t a3 = f2h2(f3.x, f3.y);
      const int kk = ks*16 + tig*2;
      #pragma unroll
      for (int nt = 0; nt < 9; ++nt) {
        const __half* base = &sb[slot][nt*8 + g][0];
        uint32_t b0 = *reinterpret_cast<const uint32_t*>(base + kk);
        uint32_t b1 = *reinterpret_cast<const uint32_t*>(base + kk + 8);
        mma16816(c[nt], a0, a1, a2, a3, b0, b1);
      }
    }
  }

  // epilogue: den is column 64 = ntile 8, col offset 0 (tig==0 lanes)
  const unsigned FULL = 0xffffffffu;
  float dlo = __shfl_sync(FULL, c[8][0], lane & ~3);
  float dhi = __shfl_sync(FULL, c[8][2], lane & ~3);
  float slo = 1.f / (dlo * 4096.f);
  float shi = 1.f / (dhi * 4096.f);
  float* o0 = out + (size_t)(b*NN + rowbase + g) * 64;
  float* o1 = out + (size_t)(b*NN + rowbase + g + 8) * 64;
  #pragma unroll
  for (int nt = 0; nt < 8; ++nt) {
    int col = nt*8 + tig*2;
    float2 v0 = make_float2(c[nt][0] * slo, c[nt][1] * slo);
    float2 v1 = make_float2(c[nt][2] * shi, c[nt][3] * shi);
    *reinterpret_cast<float2*>(o0 + col) = v0;
    *reinterpret_cast<float2*>(o1 + col) = v1;
  }
}

// ---------------- launch ----------------
extern "C" void kernel_launch(void* const* d_in, const int* in_sizes, int n_in,
                              void* d_out, int out_size) {
  const float* F     = (const float*)d_in[0];  // [4,4096,256]
  const float* adj   = (const float*)d_in[1];  // [4,4096,4096]
  const float* W_fc  = (const float*)d_in[2];  // [256,256]
  const float* b_fc  = (const float*)d_in[3];  // [256]
  const float* W_attn= (const float*)d_in[4];  // [4,512]
  float* out = (float*)d_out;                  // [4,4096,64]

  k0a<<<1, 256>>>(W_fc, b_fc, W_attn);
  k0b<<<256, 96>>>(W_fc);
  k1<<<dim3(128, 2), 128>>>(F);
  k2<<<4, 256>>>();
  k3<<<dim3(64, 4), 256>>>();
  k4<<<dim3(32, 4), 256>>>(adj, out);
}

// round 5
// speedup vs baseline: 1.6484x; 1.6484x over previous
#include <cuda_runtime.h>
#include <cuda_fp16.h>
#include <cstdint>
#include <cstddef>

#define NB 4
#define NN 4096
#define ND 256
#define NOUT 64
#define NROWS (NB*NN)

// ---------------- device scratch ----------------
__device__ __align__(16) float g_avec[256];
__device__ __align__(16) float g_beff[64];
__device__ float g_csrc;
__device__ __align__(16) float g_Wc[256*66];          // [d][l]: l<64 Weff, l=64 a_vec, l=65 zero
__device__ __align__(16) float g_hs[(size_t)NROWS*64];
__device__ __align__(16) float g_src[NROWS];
__device__ unsigned g_maxu[NB];
__device__ __align__(16) __half g_whT[(size_t)NB*72*4096]; // [b][l(72)][j]; l=64 is w, 65..71 zero

// ---------------- helpers ----------------
static __device__ __forceinline__ void cp16(void* s, const void* g) {
  uint32_t sa = (uint32_t)__cvta_generic_to_shared(s);
  asm volatile("cp.async.cg.shared.global [%0], [%1], 16;\n" :: "r"(sa), "l"(g));
}
#define CP_COMMIT() asm volatile("cp.async.commit_group;\n" ::)
#define CP_WAIT2()  asm volatile("cp.async.wait_group 2;\n" ::)

static __device__ __forceinline__ uint32_t f2h2(float x, float y) {
  __half2 h = __floats2half2_rn(x, y);
  return *reinterpret_cast<uint32_t*>(&h);
}
static __device__ __forceinline__ unsigned encf(float f) {
  unsigned u = __float_as_uint(f);
  return (u & 0x80000000u) ? ~u : (u | 0x80000000u);
}
static __device__ __forceinline__ float decf(unsigned u) {
  return __uint_as_float((u & 0x80000000u) ? (u & 0x7fffffffu) : ~u);
}
static __device__ __forceinline__ void mma16816(float c[4],
    uint32_t a0, uint32_t a1, uint32_t a2, uint32_t a3, uint32_t b0, uint32_t b1) {
  asm volatile("mma.sync.aligned.m16n8k16.row.col.f32.f16.f16.f32 "
    "{%0,%1,%2,%3}, {%4,%5,%6,%7}, {%8,%9}, {%0,%1,%2,%3};\n"
    : "+f"(c[0]), "+f"(c[1]), "+f"(c[2]), "+f"(c[3])
    : "r"(a0), "r"(a1), "r"(a2), "r"(a3), "r"(b0), "r"(b1));
}

// ---------------- K0a: fold attention weights + reset max ----------------
__global__ void k0a(const float* __restrict__ W_fc, const float* __restrict__ b_fc,
                    const float* __restrict__ W_attn) {
  __shared__ float ws[256];
  const int t = threadIdx.x;
  if (t < NB) g_maxu[t] = 0u;
  {
    int h = t >> 6, o = t & 63;
    float s = 0.f;
    #pragma unroll
    for (int k = 0; k < 4; k++) s += W_attn[k*512 + h*128 + o];
    ws[t] = 0.25f * s;
  }
  __syncthreads();
  {
    float a0 = 0.f, a1 = 0.f;
    for (int c = 0; c < 256; c += 2) {
      a0 += ws[c]   * W_fc[(size_t)c*256 + t];
      a1 += ws[c+1] * W_fc[(size_t)(c+1)*256 + t];
    }
    g_avec[t] = a0 + a1;
  }
  if (t < 64) {
    float bb = 0.f;
    #pragma unroll
    for (int h = 0; h < 4; h++) bb += b_fc[h*64 + t];
    g_beff[t] = bb;
  }
  if (t == 0) {
    float cs = 0.f;
    for (int c = 0; c < 256; c++) cs += b_fc[c] * ws[c];
    g_csrc = cs;
  }
}

// ---------------- K0b: combined weight matrix [256][66] ----------------
__global__ void k0b(const float* __restrict__ W_fc) {
  int d = blockIdx.x;
  int l = threadIdx.x;
  if (l >= 66) return;
  float v = 0.f;
  if (l < 64) {
    #pragma unroll
    for (int h = 0; h < 4; h++) v += W_fc[(size_t)(h*64 + l)*256 + d];
  } else if (l == 64) {
    v = g_avec[d];
  }
  g_Wc[d*66 + l] = v;
}

// ---------------- K1: hs = F@Weff + beff ; src = F@a_vec + csrc ; fused src-max ----------------
__global__ void __launch_bounds__(128) k1(const float* __restrict__ F) {
  __shared__ float Fs[128][33];
  __shared__ float Ws[32][66];
  __shared__ float red[128];
  const int t = threadIdx.x;
  const int rowbase = blockIdx.x * 128;
  const int l0 = blockIdx.y * 33;   // 0 or 33
  float acc[33];
  #pragma unroll
  for (int i = 0; i < 33; i++) acc[i] = 0.f;

  for (int c = 0; c < 8; ++c) {
    const int d0 = c * 32;
    __syncthreads();
    #pragma unroll
    for (int i = 0; i < 32; ++i) {
      int idx = i*128 + t;
      int rr = idx >> 5, dd = idx & 31;
      Fs[rr][dd] = F[(size_t)(rowbase + rr)*256 + d0 + dd];
    }
    for (int i = t; i < 32*66; i += 128) {
      int dd = i / 66, l = i - dd*66;
      Ws[dd][l] = g_Wc[(d0 + dd)*66 + l];
    }
    __syncthreads();
    #pragma unroll 4
    for (int dd = 0; dd < 32; ++dd) {
      float f = Fs[t][dd];
      #pragma unroll
      for (int i = 0; i < 33; ++i) acc[i] = fmaf(f, Ws[dd][l0 + i], acc[i]);
    }
  }
  const int row = rowbase + t;
  float srcval = 0.f;
  #pragma unroll
  for (int i = 0; i < 33; ++i) {
    int l = l0 + i;
    if (l < 64)       g_hs[(size_t)row*64 + l] = acc[i] + g_beff[l];
    else if (l == 64) { srcval = acc[i] + g_csrc; g_src[row] = srcval; }
  }
  if (l0 == 33) {  // this block produced src values: reduce block max, one atomic
    __syncthreads();
    red[t] = srcval;
    __syncthreads();
    #pragma unroll
    for (int s = 64; s > 0; s >>= 1) {
      if (t < s) red[t] = fmaxf(red[t], red[t + s]);
      __syncthreads();
    }
    if (t == 0) atomicMax(&g_maxu[rowbase >> 12], encf(red[0]));
  }
}

// ---------------- K3: build transposed fp16 [w*hs | w | 0] ----------------
__global__ void __launch_bounds__(256) k3() {
  __shared__ float sh[64][65];
  __shared__ float wsm[64];
  const int t = threadIdx.x;
  const int jbase = blockIdx.x * 64;
  const int b = blockIdx.y;
  for (int idx = t; idx < 64*64; idx += 256) {
    int jl = idx >> 6, l = idx & 63;
    sh[jl][l] = g_hs[(size_t)(b*NN + jbase + jl)*64 + l];
  }
  if (t < 64) {
    wsm[t] = expf(g_src[b*NN + jbase + t] - decf(g_maxu[b]));
  }
  __syncthreads();
  for (int idx = t; idx < 72*64; idx += 256) {
    int l = idx >> 6, jl = idx & 63;
    float v;
    if (l < 64)       v = wsm[jl] * sh[jl][l];
    else if (l == 64) v = wsm[jl];
    else              v = 0.f;
    g_whT[((size_t)b*72 + l)*4096 + jbase + jl] = __float2half(v);
  }
}

// ---------------- K4: per-batch C[4096,72] = adj @ [wh|w], fused normalize ----------------
__global__ void __launch_bounds__(256) k4(const float* __restrict__ adj,
                                          float* __restrict__ out) {
  __shared__ __half sb[4][72][40];   // 80B-padded rows: conflict-free fragment loads
  const int t = threadIdx.x;
  const int warp = t >> 5, lane = t & 31;
  const int g = lane >> 2, tig = lane & 3;
  const int b = blockIdx.y;
  const int rowbase = blockIdx.x * 128 + warp * 16;
  const float* adjb = adj + ((size_t)b << 24);
  const __half* wht = g_whT + (size_t)b * 72 * 4096;

  float c[9][4];
  #pragma unroll
  for (int nt = 0; nt < 9; nt++) {
    #pragma unroll
    for (int i = 0; i < 4; i++) c[nt][i] = 0.f;
  }

  const float* arow0 = adjb + (size_t)(rowbase + g) * 4096;
  const float* arow1 = adjb + (size_t)(rowbase + g + 8) * 4096;

  auto issueB = [&](int sk) {
    const int slot = sk & 3;
    const int kbase = sk * 32;
    for (int i = t; i < 288; i += 256) {
      int n = i >> 2, cc = i & 3;
      cp16(&sb[slot][n][cc*8], wht + (size_t)n*4096 + kbase + cc*8);
    }
  };

  // depth-4 register pipeline for adj (prefetch distance 3)
  float2 buf[4][8];
  auto loadA = [&](int sk, int s) {
    #pragma unroll
    for (int ks = 0; ks < 2; ++ks) {
      const int k0 = sk*32 + ks*16 + tig*2;
      buf[s][ks*4+0] = __ldcs(reinterpret_cast<const float2*>(arow0 + k0));
      buf[s][ks*4+1] = __ldcs(reinterpret_cast<const float2*>(arow1 + k0));
      buf[s][ks*4+2] = __ldcs(reinterpret_cast<const float2*>(arow0 + k0 + 8));
      buf[s][ks*4+3] = __ldcs(reinterpret_cast<const float2*>(arow1 + k0 + 8));
    }
  };

  loadA(0, 0); loadA(1, 1); loadA(2, 2);
  issueB(0); CP_COMMIT();
  issueB(1); CP_COMMIT();
  issueB(2); CP_COMMIT();

  #pragma unroll 4
  for (int sk = 0; sk < 128; ++sk) {
    const int s = sk & 3;
    // convert current stage -> fp16 A fragments (register-dependency waits the loads)
    uint32_t a[2][4];
    #pragma unroll
    for (int ks = 0; ks < 2; ++ks) {
      a[ks][0] = f2h2(buf[s][ks*4+0].x, buf[s][ks*4+0].y);
      a[ks][1] = f2h2(buf[s][ks*4+1].x, buf[s][ks*4+1].y);
      a[ks][2] = f2h2(buf[s][ks*4+2].x, buf[s][ks*4+2].y);
      a[ks][3] = f2h2(buf[s][ks*4+3].x, buf[s][ks*4+3].y);
    }
    if (sk + 3 < 128) loadA(sk + 3, (sk + 3) & 3);  // refill just-freed stage
    CP_WAIT2();
    __syncthreads();
    if (sk + 3 < 128) issueB(sk + 3);
    CP_COMMIT();                       // empty commits in tail keep group count uniform
    const int slot = sk & 3;
    #pragma unroll
    for (int ks = 0; ks < 2; ++ks) {
      const int kk = ks*16 + tig*2;
      #pragma unroll
      for (int nt = 0; nt < 9; ++nt) {
        const __half* base = &sb[slot][nt*8 + g][0];
        uint32_t b0 = *reinterpret_cast<const uint32_t*>(base + kk);
        uint32_t b1 = *reinterpret_cast<const uint32_t*>(base + kk + 8);
        mma16816(c[nt], a[ks][0], a[ks][1], a[ks][2], a[ks][3], b0, b1);
      }
    }
  }

  // epilogue: den is column 64 = ntile 8, col offset 0 (tig==0 lanes)
  const unsigned FULL = 0xffffffffu;
  float dlo = __shfl_sync(FULL, c[8][0], lane & ~3);
  float dhi = __shfl_sync(FULL, c[8][2], lane & ~3);
  float slo = 1.f / (dlo * 4096.f);
  float shi = 1.f / (dhi * 4096.f);
  float* o0 = out + (size_t)(b*NN + rowbase + g) * 64;
  float* o1 = out + (size_t)(b*NN + rowbase + g + 8) * 64;
  #pragma unroll
  for (int nt = 0; nt < 8; ++nt) {
    int col = nt*8 + tig*2;
    float2 v0 = make_float2(c[nt][0] * slo, c[nt][1] * slo);
    float2 v1 = make_float2(c[nt][2] * shi, c[nt][3] * shi);
    *reinterpret_cast<float2*>(o0 + col) = v0;
    *reinterpret_cast<float2*>(o1 + col) = v1;
  }
}

// ---------------- launch ----------------
extern "C" void kernel_launch(void* const* d_in, const int* in_sizes, int n_in,
                              void* d_out, int out_size) {
  const float* F     = (const float*)d_in[0];  // [4,4096,256]
  const float* adj   = (const float*)d_in[1];  // [4,4096,4096]
  const float* W_fc  = (const float*)d_in[2];  // [256,256]
  const float* b_fc  = (const float*)d_in[3];  // [256]
  const float* W_attn= (const float*)d_in[4];  // [4,512]
  float* out = (float*)d_out;                  // [4,4096,64]

  k0a<<<1, 256>>>(W_fc, b_fc, W_attn);
  k0b<<<256, 96>>>(W_fc);
  k1<<<dim3(128, 2), 128>>>(F);
  k3<<<dim3(64, 4), 256>>>();
  k4<<<dim3(32, 4), 256>>>(adj, out);
}